// round 1
// baseline (speedup 1.0000x reference)
#include <cuda_runtime.h>
#include <cstdint>

#define BB  8
#define NN  4096
#define SS  1024
#define CIN 64
#define NC  (BB*SS)          /* 8192 centers */

#define OUT_X_ELEMS   (NC*640)            /* 5242880 */
#define OUT_POS_OFF   OUT_X_ELEMS
#define OUT_BATCH_OFF (OUT_X_ELEMS + NC*3)

#define INF_F __int_as_float(0x7f800000)

// ---------------- scratch (__device__ globals: allocation-free contract) ---------
__device__ int   g_fps_idx[NC];
__device__ float g_centers[NC*3];
__device__ int   g_nbr[NC*64];
__device__ int   g_cnt[NC];
__device__ float g_bufA[(size_t)NC*64*128];   // 256 MB: feat (67w) then h2
__device__ float g_bufB[(size_t)NC*64*128];   // 256 MB: h1

// =================================================================================
// 1) Farthest point sampling: one block per cloud. Arithmetic replicates
//    sum((p - c)**2) as ((dx*dx + dy*dy) + dz*dz) with NO fma contraction,
//    argmax = first max index (matches jnp.argmax).
// =================================================================================
__global__ void __launch_bounds__(512) fps_kernel(const float* __restrict__ pos)
{
    const int b   = blockIdx.x;
    const int tid = threadIdx.x;
    const float* p = pos + (size_t)b * NN * 3;

    float px[8], py[8], pz[8], md[8];
#pragma unroll
    for (int i = 0; i < 8; i++) {
        int j = tid * 8 + i;
        px[i] = p[j*3+0]; py[i] = p[j*3+1]; pz[i] = p[j*3+2];
        md[i] = INF_F;
    }

    __shared__ float s_c[3];
    __shared__ float s_v[16];
    __shared__ int   s_i[16];

    if (tid == 0) {
        g_fps_idx[b*SS] = 0;
        s_c[0] = p[0]; s_c[1] = p[1]; s_c[2] = p[2];
        size_t o = (size_t)b * SS * 3;
        g_centers[o] = p[0]; g_centers[o+1] = p[1]; g_centers[o+2] = p[2];
    }
    __syncthreads();

    for (int s = 1; s < SS; s++) {
        const float cx = s_c[0], cy = s_c[1], cz = s_c[2];
        float bv = -1.0f; int bi = 0;
#pragma unroll
        for (int i = 0; i < 8; i++) {
            float dx = __fsub_rn(px[i], cx);
            float dy = __fsub_rn(py[i], cy);
            float dz = __fsub_rn(pz[i], cz);
            float d2 = __fadd_rn(__fadd_rn(__fmul_rn(dx,dx), __fmul_rn(dy,dy)),
                                 __fmul_rn(dz,dz));
            md[i] = fminf(md[i], d2);
            if (md[i] > bv) { bv = md[i]; bi = tid*8 + i; }
        }
#pragma unroll
        for (int off = 16; off > 0; off >>= 1) {
            float ov = __shfl_down_sync(0xffffffffu, bv, off);
            int   oi = __shfl_down_sync(0xffffffffu, bi, off);
            if (ov > bv || (ov == bv && oi < bi)) { bv = ov; bi = oi; }
        }
        if ((tid & 31) == 0) { s_v[tid>>5] = bv; s_i[tid>>5] = bi; }
        __syncthreads();
        if (tid < 32) {
            float v2 = (tid < 16) ? s_v[tid] : -1.0f;
            int   i2 = (tid < 16) ? s_i[tid] : 0x7fffffff;
#pragma unroll
            for (int off = 8; off > 0; off >>= 1) {
                float ov = __shfl_down_sync(0xffffffffu, v2, off);
                int   oi = __shfl_down_sync(0xffffffffu, i2, off);
                if (ov > v2 || (ov == v2 && oi < i2)) { v2 = ov; i2 = oi; }
            }
            if (tid == 0) {
                g_fps_idx[b*SS + s] = i2;
                float nx = p[i2*3+0], ny = p[i2*3+1], nz = p[i2*3+2];
                s_c[0] = nx; s_c[1] = ny; s_c[2] = nz;
                size_t o = ((size_t)b*SS + s) * 3;
                g_centers[o] = nx; g_centers[o+1] = ny; g_centers[o+2] = nz;
            }
        }
        __syncthreads();
    }
}

// =================================================================================
// 2) Radius ball query + exact top-K: one block per center. Candidates within r2
//    packed as (f32 d2 bits << 32) | idx  -> bitonic sort -> first K.
//    Exactly reproduces jax.lax.top_k tie-breaking (lower index first).
// =================================================================================
__global__ void __launch_bounds__(256) nbr_kernel(const float* __restrict__ pos,
                                                  float r2, int Kn)
{
    __shared__ unsigned long long keys[4096];
    __shared__ int s_count;
    const int ci  = blockIdx.x;
    const int b   = ci / SS;
    const int tid = threadIdx.x;
    if (tid == 0) s_count = 0;
    __syncthreads();

    const float cx = g_centers[ci*3+0], cy = g_centers[ci*3+1], cz = g_centers[ci*3+2];
    const float* p = pos + (size_t)b * NN * 3;

    for (int j = tid; j < NN; j += 256) {
        float dx = __fsub_rn(cx, p[j*3+0]);
        float dy = __fsub_rn(cy, p[j*3+1]);
        float dz = __fsub_rn(cz, p[j*3+2]);
        float d2 = __fadd_rn(__fadd_rn(__fmul_rn(dx,dx), __fmul_rn(dy,dy)),
                             __fmul_rn(dz,dz));
        if (d2 <= r2) {
            int w = atomicAdd(&s_count, 1);
            keys[w] = (((unsigned long long)__float_as_uint(d2)) << 32) | (unsigned)j;
        }
    }
    __syncthreads();
    const int M = s_count;                 // <= NN, keys[] sized for worst case
    int n = 16;
    while (n < M || n < Kn) n <<= 1;
    for (int i = M + tid; i < n; i += 256) keys[i] = 0xFFFFFFFFFFFFFFFFULL;
    __syncthreads();

    for (int size = 2; size <= n; size <<= 1) {
        for (int stride = size >> 1; stride > 0; stride >>= 1) {
            for (int i = tid; i < (n >> 1); i += 256) {
                int p0 = 2*i - (i & (stride - 1));
                int p1 = p0 + stride;
                unsigned long long a = keys[p0], c = keys[p1];
                bool asc = ((p0 & size) == 0);
                if (asc ? (a > c) : (a < c)) { keys[p0] = c; keys[p1] = a; }
            }
            __syncthreads();
        }
    }

    for (int k = tid; k < Kn; k += 256) {
        int j = (k < M) ? (int)(keys[k] & 0xFFFFFFFFu) : 0;
        g_nbr[(size_t)ci * Kn + k] = b * NN + j;    // global point row
    }
    if (tid == 0) g_cnt[ci] = (M < Kn) ? M : Kn;
}

// =================================================================================
// 3) Gather features: row r = (center, k) -> [x_j(64) , pos_j - center(3)]
// =================================================================================
__global__ void __launch_bounds__(256) gather_kernel(const float* __restrict__ x,
                                                     const float* __restrict__ pos,
                                                     int Kn, float* __restrict__ feat)
{
    const int warp = threadIdx.x >> 5, lane = threadIdx.x & 31;
    const long row = (long)blockIdx.x * 8 + warp;
    const int  ci  = (int)(row / Kn);
    const int  j   = g_nbr[(size_t)ci * Kn + (row % Kn)];
    float* fr = feat + (size_t)row * 67;
    for (int c = lane; c < 64; c += 32) fr[c] = x[(size_t)j * CIN + c];
    if (lane < 3)
        fr[64 + lane] = __fsub_rn(pos[(size_t)j*3 + lane], g_centers[(size_t)ci*3 + lane]);
}

// =================================================================================
// 4) Tiled fp32 GEMM + bias + ReLU.  Block tile 128x64, BK=16, 128 threads,
//    8x8 register micro-tile (4 FMA per LDS word -> at the smem BW ceiling).
// =================================================================================
__global__ void __launch_bounds__(128) gemm_relu(const float* __restrict__ A,
                                                 const float* __restrict__ W,
                                                 const float* __restrict__ bias,
                                                 float* __restrict__ C,
                                                 int Kc, int Nc)
{
    __shared__ float As[16][128];
    __shared__ float Bs[16][64];
    const int tid = threadIdx.x;
    const int tx  = tid & 7, ty = tid >> 3;
    const int row0 = blockIdx.x * 128;
    const int col0 = blockIdx.y * 64;

    float acc[8][8];
#pragma unroll
    for (int i = 0; i < 8; i++)
#pragma unroll
        for (int j = 0; j < 8; j++) acc[i][j] = 0.f;

    for (int kk = 0; kk < Kc; kk += 16) {
#pragma unroll
        for (int t = 0; t < 16; t++)
            As[t][tid] = (kk + t < Kc) ? A[(size_t)(row0 + tid) * Kc + kk + t] : 0.f;
#pragma unroll
        for (int t = 0; t < 8; t++) {
            int i = t * 128 + tid;
            int k = i >> 6, n = i & 63;
            Bs[k][n] = (kk + k < Kc) ? W[(size_t)(kk + k) * Nc + col0 + n] : 0.f;
        }
        __syncthreads();
#pragma unroll
        for (int k = 0; k < 16; k++) {
            float a[8], b[8];
            *(float4*)&a[0] = *(const float4*)&As[k][ty*8];
            *(float4*)&a[4] = *(const float4*)&As[k][ty*8+4];
            *(float4*)&b[0] = *(const float4*)&Bs[k][tx*8];
            *(float4*)&b[4] = *(const float4*)&Bs[k][tx*8+4];
#pragma unroll
            for (int i = 0; i < 8; i++)
#pragma unroll
                for (int j = 0; j < 8; j++)
                    acc[i][j] = fmaf(a[i], b[j], acc[i][j]);
        }
        __syncthreads();
    }
#pragma unroll
    for (int j = 0; j < 8; j++) {
        float bj = bias[col0 + tx*8 + j];
#pragma unroll
        for (int i = 0; i < 8; i++) {
            float v = fmaxf(acc[i][j] + bj, 0.f);
            C[(size_t)(row0 + ty*8 + i) * Nc + col0 + tx*8 + j] = v;
        }
    }
}

// =================================================================================
// 5) Last-layer GEMM + bias + ReLU + masked segment-max fused in the epilogue.
//    Kn | 128 so every block covers whole centers; each thread's 8 rows sit in
//    one center; cross-thread max via smem. Writes out[center][colOff + col].
// =================================================================================
__global__ void __launch_bounds__(128) gemm_relu_max(const float* __restrict__ A,
                                                     const float* __restrict__ W,
                                                     const float* __restrict__ bias,
                                                     float* __restrict__ out,
                                                     int Kc, int Nc, int Kn, int colOff)
{
    __shared__ float As[16][128];
    __shared__ float Bs[16][64];
    __shared__ float red[16][64];
    const int tid = threadIdx.x;
    const int tx  = tid & 7, ty = tid >> 3;
    const int row0 = blockIdx.x * 128;
    const int col0 = blockIdx.y * 64;

    float acc[8][8];
#pragma unroll
    for (int i = 0; i < 8; i++)
#pragma unroll
        for (int j = 0; j < 8; j++) acc[i][j] = 0.f;

    for (int kk = 0; kk < Kc; kk += 16) {
#pragma unroll
        for (int t = 0; t < 16; t++)
            As[t][tid] = (kk + t < Kc) ? A[(size_t)(row0 + tid) * Kc + kk + t] : 0.f;
#pragma unroll
        for (int t = 0; t < 8; t++) {
            int i = t * 128 + tid;
            int k = i >> 6, n = i & 63;
            Bs[k][n] = (kk + k < Kc) ? W[(size_t)(kk + k) * Nc + col0 + n] : 0.f;
        }
        __syncthreads();
#pragma unroll
        for (int k = 0; k < 16; k++) {
            float a[8], b[8];
            *(float4*)&a[0] = *(const float4*)&As[k][ty*8];
            *(float4*)&a[4] = *(const float4*)&As[k][ty*8+4];
            *(float4*)&b[0] = *(const float4*)&Bs[k][tx*8];
            *(float4*)&b[4] = *(const float4*)&Bs[k][tx*8+4];
#pragma unroll
            for (int i = 0; i < 8; i++)
#pragma unroll
                for (int j = 0; j < 8; j++)
                    acc[i][j] = fmaf(a[i], b[j], acc[i][j]);
        }
        __syncthreads();
    }

    // epilogue: bias + relu + max over valid neighbors of this thread's rows
    const int cglob = (row0 + ty*8) / Kn;        // all 8 rows in one center
    const int ccnt  = g_cnt[cglob];
    float bj[8];
#pragma unroll
    for (int j = 0; j < 8; j++) bj[j] = bias[col0 + tx*8 + j];
    float m[8];
#pragma unroll
    for (int j = 0; j < 8; j++) m[j] = -INF_F;
#pragma unroll
    for (int i = 0; i < 8; i++) {
        int kidx = (ty*8 + i) % Kn;              // row0 % Kn == 0
        if (kidx < ccnt) {
#pragma unroll
            for (int j = 0; j < 8; j++)
                m[j] = fmaxf(m[j], fmaxf(acc[i][j] + bj[j], 0.f));
        }
    }
#pragma unroll
    for (int j = 0; j < 8; j++) red[ty][tx*8 + j] = m[j];
    __syncthreads();

    const int tper = Kn >> 3;                    // threads (ty's) per center
    if ((ty & (tper - 1)) == 0) {
#pragma unroll
        for (int j = 0; j < 8; j++) {
            float v = red[ty][tx*8 + j];
            for (int t = 1; t < tper; t++) v = fmaxf(v, red[ty + t][tx*8 + j]);
            out[(size_t)cglob * 640 + colOff + col0 + tx*8 + j] = v;
        }
    }
}

// =================================================================================
// 6) new_pos / new_batch tail
// =================================================================================
__global__ void tail_kernel(float* __restrict__ out, int writePos, int writeBatch)
{
    int i = blockIdx.x * blockDim.x + threadIdx.x;
    if (i >= NC) return;
    if (writePos) {
        out[OUT_POS_OFF + i*3 + 0] = g_centers[i*3+0];
        out[OUT_POS_OFF + i*3 + 1] = g_centers[i*3+1];
        out[OUT_POS_OFF + i*3 + 2] = g_centers[i*3+2];
    }
    if (writeBatch) out[OUT_BATCH_OFF + i] = (float)(i / SS);
}

// =================================================================================
extern "C" void kernel_launch(void* const* d_in, const int* in_sizes, int n_in,
                              void* d_out, int out_size)
{
    const float* x   = (const float*)d_in[0];
    const float* pos = (const float*)d_in[1];
    const float* W[3][3];
    const float* bv[3][3];
    int ii = 3;
    for (int s = 0; s < 3; s++)
        for (int l = 0; l < 3; l++) {
            W[s][l]  = (const float*)d_in[ii++];
            bv[s][l] = (const float*)d_in[ii++];
        }
    float* out = (float*)d_out;

    void *pA = nullptr, *pB = nullptr;
    cudaGetSymbolAddress(&pA, g_bufA);
    cudaGetSymbolAddress(&pB, g_bufB);
    float* bufA = (float*)pA;
    float* bufB = (float*)pB;

    fps_kernel<<<BB, 512>>>(pos);

    const int writePos   = (out_size >= OUT_POS_OFF + NC*3);
    const int writeBatch = (out_size >= OUT_BATCH_OFF + NC);
    tail_kernel<<<(NC + 255)/256, 256>>>(out, writePos, writeBatch);

    const int   Kl[3]   = {16, 32, 64};
    const float r2l[3]  = {(float)(0.1*0.1), (float)(0.2*0.2), (float)(0.4*0.4)};
    const int   c1[3]   = {64, 128, 128};
    const int   c2[3]   = {64, 128, 128};
    const int   c3[3]   = {128, 256, 256};
    const int   coff[3] = {0, 128, 384};

    for (int s = 0; s < 3; s++) {
        const int K = Kl[s];
        const int R = NC * K;
        nbr_kernel<<<NC, 256>>>(pos, r2l[s], K);
        gather_kernel<<<R/8, 256>>>(x, pos, K, bufA);
        gemm_relu<<<dim3(R/128, c1[s]/64), 128>>>(bufA, W[s][0], bv[s][0], bufB, 67,    c1[s]);
        gemm_relu<<<dim3(R/128, c2[s]/64), 128>>>(bufB, W[s][1], bv[s][1], bufA, c1[s], c2[s]);
        gemm_relu_max<<<dim3(R/128, c3[s]/64), 128>>>(bufA, W[s][2], bv[s][2], out,
                                                      c2[s], c3[s], K, coff[s]);
    }
}

// round 2
// speedup vs baseline: 1.5503x; 1.5503x over previous
#include <cuda_runtime.h>
#include <cstdint>

#define BB  8
#define NN  4096
#define SS  1024
#define CIN 64
#define NC  (BB*SS)          /* 8192 centers */
#define NPTS (BB*NN)         /* 32768 points */

#define OUT_X_ELEMS   (NC*640)
#define OUT_POS_OFF   OUT_X_ELEMS
#define OUT_BATCH_OFF (OUT_X_ELEMS + NC*3)

#define INF_F __int_as_float(0x7f800000)

// ---------------- scratch (__device__ globals: allocation-free contract) ---------
__device__ int   g_fps_idx[NC];
__device__ float g_centers[NC*3];
__device__ int   g_nbr[NC*64];
__device__ int   g_cnt[NC];
__device__ float g_xw[(size_t)NPTS*320];      // 42 MB: x@Wx + b, all 3 scales
__device__ float g_bufA[(size_t)NC*64*128];   // 268 MB: h2
__device__ float g_bufB[(size_t)NC*64*128];   // 268 MB: h1

// =================================================================================
// 1) Farthest point sampling (unchanged — correctness-critical arithmetic)
// =================================================================================
__global__ void __launch_bounds__(512) fps_kernel(const float* __restrict__ pos)
{
    const int b   = blockIdx.x;
    const int tid = threadIdx.x;
    const float* p = pos + (size_t)b * NN * 3;

    float px[8], py[8], pz[8], md[8];
#pragma unroll
    for (int i = 0; i < 8; i++) {
        int j = tid * 8 + i;
        px[i] = p[j*3+0]; py[i] = p[j*3+1]; pz[i] = p[j*3+2];
        md[i] = INF_F;
    }

    __shared__ float s_c[3];
    __shared__ float s_v[16];
    __shared__ int   s_i[16];

    if (tid == 0) {
        g_fps_idx[b*SS] = 0;
        s_c[0] = p[0]; s_c[1] = p[1]; s_c[2] = p[2];
        size_t o = (size_t)b * SS * 3;
        g_centers[o] = p[0]; g_centers[o+1] = p[1]; g_centers[o+2] = p[2];
    }
    __syncthreads();

    for (int s = 1; s < SS; s++) {
        const float cx = s_c[0], cy = s_c[1], cz = s_c[2];
        float bv = -1.0f; int bi = 0;
#pragma unroll
        for (int i = 0; i < 8; i++) {
            float dx = __fsub_rn(px[i], cx);
            float dy = __fsub_rn(py[i], cy);
            float dz = __fsub_rn(pz[i], cz);
            float d2 = __fadd_rn(__fadd_rn(__fmul_rn(dx,dx), __fmul_rn(dy,dy)),
                                 __fmul_rn(dz,dz));
            md[i] = fminf(md[i], d2);
            if (md[i] > bv) { bv = md[i]; bi = tid*8 + i; }
        }
#pragma unroll
        for (int off = 16; off > 0; off >>= 1) {
            float ov = __shfl_down_sync(0xffffffffu, bv, off);
            int   oi = __shfl_down_sync(0xffffffffu, bi, off);
            if (ov > bv || (ov == bv && oi < bi)) { bv = ov; bi = oi; }
        }
        if ((tid & 31) == 0) { s_v[tid>>5] = bv; s_i[tid>>5] = bi; }
        __syncthreads();
        if (tid < 32) {
            float v2 = (tid < 16) ? s_v[tid] : -1.0f;
            int   i2 = (tid < 16) ? s_i[tid] : 0x7fffffff;
#pragma unroll
            for (int off = 8; off > 0; off >>= 1) {
                float ov = __shfl_down_sync(0xffffffffu, v2, off);
                int   oi = __shfl_down_sync(0xffffffffu, i2, off);
                if (ov > v2 || (ov == v2 && oi < i2)) { v2 = ov; i2 = oi; }
            }
            if (tid == 0) {
                g_fps_idx[b*SS + s] = i2;
                float nx = p[i2*3+0], ny = p[i2*3+1], nz = p[i2*3+2];
                s_c[0] = nx; s_c[1] = ny; s_c[2] = nz;
                size_t o = ((size_t)b*SS + s) * 3;
                g_centers[o] = nx; g_centers[o+1] = ny; g_centers[o+2] = nz;
            }
        }
        __syncthreads();
    }
}

// =================================================================================
// 2) Radius ball query + exact top-K (unchanged)
// =================================================================================
__global__ void __launch_bounds__(256) nbr_kernel(const float* __restrict__ pos,
                                                  float r2, int Kn)
{
    __shared__ unsigned long long keys[4096];
    __shared__ int s_count;
    const int ci  = blockIdx.x;
    const int b   = ci / SS;
    const int tid = threadIdx.x;
    if (tid == 0) s_count = 0;
    __syncthreads();

    const float cx = g_centers[ci*3+0], cy = g_centers[ci*3+1], cz = g_centers[ci*3+2];
    const float* p = pos + (size_t)b * NN * 3;

    for (int j = tid; j < NN; j += 256) {
        float dx = __fsub_rn(cx, p[j*3+0]);
        float dy = __fsub_rn(cy, p[j*3+1]);
        float dz = __fsub_rn(cz, p[j*3+2]);
        float d2 = __fadd_rn(__fadd_rn(__fmul_rn(dx,dx), __fmul_rn(dy,dy)),
                             __fmul_rn(dz,dz));
        if (d2 <= r2) {
            int w = atomicAdd(&s_count, 1);
            keys[w] = (((unsigned long long)__float_as_uint(d2)) << 32) | (unsigned)j;
        }
    }
    __syncthreads();
    const int M = s_count;
    int n = 16;
    while (n < M || n < Kn) n <<= 1;
    for (int i = M + tid; i < n; i += 256) keys[i] = 0xFFFFFFFFFFFFFFFFULL;
    __syncthreads();

    for (int size = 2; size <= n; size <<= 1) {
        for (int stride = size >> 1; stride > 0; stride >>= 1) {
            for (int i = tid; i < (n >> 1); i += 256) {
                int p0 = 2*i - (i & (stride - 1));
                int p1 = p0 + stride;
                unsigned long long a = keys[p0], c = keys[p1];
                bool asc = ((p0 & size) == 0);
                if (asc ? (a > c) : (a < c)) { keys[p0] = c; keys[p1] = a; }
            }
            __syncthreads();
        }
    }

    for (int k = tid; k < Kn; k += 256) {
        int j = (k < M) ? (int)(keys[k] & 0xFFFFFFFFu) : 0;
        g_nbr[(size_t)ci * Kn + k] = b * NN + j;
    }
    if (tid == 0) g_cnt[ci] = (M < Kn) ? M : Kn;
}

// =================================================================================
// 3) Double-buffered fp32 GEMM (+bias, optional ReLU). BM=128, BN=64, BK=16,
//    128 threads, 8x8 micro-tile, register-staged prefetch, 1 sync / tile.
//    Requires Kc % 16 == 0, rows % 128 == 0, cols % 64 == 0.
// =================================================================================
__global__ void __launch_bounds__(128) gemm_db(const float* __restrict__ A,
                                               const float* __restrict__ W,
                                               const float* __restrict__ bias,
                                               float* __restrict__ C,
                                               int Kc, int Nc, int doRelu)
{
    __shared__ float As[2][16][128];
    __shared__ float Bs[2][16][64];
    const int tid = threadIdx.x;
    const int tx  = tid & 7, ty = tid >> 3;
    const int row0 = blockIdx.x * 128;
    const int col0 = blockIdx.y * 64;

    float acc[8][8];
#pragma unroll
    for (int i = 0; i < 8; i++)
#pragma unroll
        for (int j = 0; j < 8; j++) acc[i][j] = 0.f;

    float regA[16], regB[8];
    const float* Arow = A + (size_t)(row0 + tid) * Kc;
    const int bk = tid >> 3;            // 0..15 : k-row of B handled by this thread
    const int bn = (tid & 7) * 8;       // 0..56 : n-offset (8 floats = 2 float4)

    // prefetch tile 0
#pragma unroll
    for (int q = 0; q < 4; q++)
        *(float4*)&regA[q*4] = *(const float4*)&Arow[q*4];
    {
        const float* Wr = W + (size_t)bk * Nc + col0 + bn;
        *(float4*)&regB[0] = *(const float4*)&Wr[0];
        *(float4*)&regB[4] = *(const float4*)&Wr[4];
    }

    int buf = 0;
    for (int kk = 0; kk < Kc; kk += 16) {
        // commit staged regs to smem[buf]
#pragma unroll
        for (int t = 0; t < 16; t++) As[buf][t][tid] = regA[t];
        *(float4*)&Bs[buf][bk][bn]   = *(float4*)&regB[0];
        *(float4*)&Bs[buf][bk][bn+4] = *(float4*)&regB[4];
        __syncthreads();

        if (kk + 16 < Kc) {
#pragma unroll
            for (int q = 0; q < 4; q++)
                *(float4*)&regA[q*4] = *(const float4*)&Arow[kk + 16 + q*4];
            const float* Wr = W + (size_t)(kk + 16 + bk) * Nc + col0 + bn;
            *(float4*)&regB[0] = *(const float4*)&Wr[0];
            *(float4*)&regB[4] = *(const float4*)&Wr[4];
        }

#pragma unroll
        for (int k = 0; k < 16; k++) {
            float a[8], b[8];
            *(float4*)&a[0] = *(const float4*)&As[buf][k][ty*8];
            *(float4*)&a[4] = *(const float4*)&As[buf][k][ty*8+4];
            *(float4*)&b[0] = *(const float4*)&Bs[buf][k][tx*8];
            *(float4*)&b[4] = *(const float4*)&Bs[buf][k][tx*8+4];
#pragma unroll
            for (int i = 0; i < 8; i++)
#pragma unroll
                for (int j = 0; j < 8; j++)
                    acc[i][j] = fmaf(a[i], b[j], acc[i][j]);
        }
        buf ^= 1;
    }

#pragma unroll
    for (int j = 0; j < 8; j++) {
        float bj = bias[col0 + tx*8 + j];
#pragma unroll
        for (int i = 0; i < 8; i++) {
            float v = acc[i][j] + bj;
            if (doRelu) v = fmaxf(v, 0.f);
            C[(size_t)(row0 + ty*8 + i) * Nc + col0 + tx*8 + j] = v;
        }
    }
}

// =================================================================================
// 4) Last-layer GEMM + bias + ReLU + masked segment-max (double buffered).
// =================================================================================
__global__ void __launch_bounds__(128) gemm_db_max(const float* __restrict__ A,
                                                   const float* __restrict__ W,
                                                   const float* __restrict__ bias,
                                                   float* __restrict__ out,
                                                   int Kc, int Nc, int Kn, int colOff)
{
    __shared__ float As[2][16][128];
    __shared__ float Bs[2][16][64];
    __shared__ float red[16][64];
    const int tid = threadIdx.x;
    const int tx  = tid & 7, ty = tid >> 3;
    const int row0 = blockIdx.x * 128;
    const int col0 = blockIdx.y * 64;

    float acc[8][8];
#pragma unroll
    for (int i = 0; i < 8; i++)
#pragma unroll
        for (int j = 0; j < 8; j++) acc[i][j] = 0.f;

    float regA[16], regB[8];
    const float* Arow = A + (size_t)(row0 + tid) * Kc;
    const int bk = tid >> 3;
    const int bn = (tid & 7) * 8;

#pragma unroll
    for (int q = 0; q < 4; q++)
        *(float4*)&regA[q*4] = *(const float4*)&Arow[q*4];
    {
        const float* Wr = W + (size_t)bk * Nc + col0 + bn;
        *(float4*)&regB[0] = *(const float4*)&Wr[0];
        *(float4*)&regB[4] = *(const float4*)&Wr[4];
    }

    int buf = 0;
    for (int kk = 0; kk < Kc; kk += 16) {
#pragma unroll
        for (int t = 0; t < 16; t++) As[buf][t][tid] = regA[t];
        *(float4*)&Bs[buf][bk][bn]   = *(float4*)&regB[0];
        *(float4*)&Bs[buf][bk][bn+4] = *(float4*)&regB[4];
        __syncthreads();

        if (kk + 16 < Kc) {
#pragma unroll
            for (int q = 0; q < 4; q++)
                *(float4*)&regA[q*4] = *(const float4*)&Arow[kk + 16 + q*4];
            const float* Wr = W + (size_t)(kk + 16 + bk) * Nc + col0 + bn;
            *(float4*)&regB[0] = *(const float4*)&Wr[0];
            *(float4*)&regB[4] = *(const float4*)&Wr[4];
        }

#pragma unroll
        for (int k = 0; k < 16; k++) {
            float a[8], b[8];
            *(float4*)&a[0] = *(const float4*)&As[buf][k][ty*8];
            *(float4*)&a[4] = *(const float4*)&As[buf][k][ty*8+4];
            *(float4*)&b[0] = *(const float4*)&Bs[buf][k][tx*8];
            *(float4*)&b[4] = *(const float4*)&Bs[buf][k][tx*8+4];
#pragma unroll
            for (int i = 0; i < 8; i++)
#pragma unroll
                for (int j = 0; j < 8; j++)
                    acc[i][j] = fmaf(a[i], b[j], acc[i][j]);
        }
        buf ^= 1;
    }

    // epilogue: bias + relu + max over valid neighbors of this thread's rows
    const int cglob = (row0 + ty*8) / Kn;
    const int ccnt  = g_cnt[cglob];
    float bj[8];
#pragma unroll
    for (int j = 0; j < 8; j++) bj[j] = bias[col0 + tx*8 + j];
    float m[8];
#pragma unroll
    for (int j = 0; j < 8; j++) m[j] = -INF_F;
#pragma unroll
    for (int i = 0; i < 8; i++) {
        int kidx = (ty*8 + i) % Kn;
        if (kidx < ccnt) {
#pragma unroll
            for (int j = 0; j < 8; j++)
                m[j] = fmaxf(m[j], fmaxf(acc[i][j] + bj[j], 0.f));
        }
    }
    __syncthreads();
#pragma unroll
    for (int j = 0; j < 8; j++) red[ty][tx*8 + j] = m[j];
    __syncthreads();

    const int tper = Kn >> 3;
    if ((ty & (tper - 1)) == 0) {
#pragma unroll
        for (int j = 0; j < 8; j++) {
            float v = red[ty][tx*8 + j];
            for (int t = 1; t < tper; t++) v = fmaxf(v, red[ty + t][tx*8 + j]);
            out[(size_t)cglob * 640 + colOff + col0 + tx*8 + j] = v;
        }
    }
}

// =================================================================================
// 5) Fused gather + layer-1: h1[row] = relu(xwb[j] + (pos_j - center)@Wp)
//    One warp per (center, k) row; Wp (3 x c1) staged in smem.
// =================================================================================
__global__ void __launch_bounds__(256) fused_l1(const float* __restrict__ pos,
                                                const float* __restrict__ xwb,
                                                const float* __restrict__ W1,
                                                int Kn, int c1,
                                                float* __restrict__ h1)
{
    __shared__ float s_wp[3*128];
    const int tid  = threadIdx.x;
    for (int i = tid; i < 3 * c1; i += 256)
        s_wp[i] = W1[(size_t)(64 + i / c1) * c1 + (i % c1)];
    __syncthreads();

    const int warp = tid >> 5, lane = tid & 31;
    const long row = (long)blockIdx.x * 8 + warp;
    const int  ci  = (int)(row / Kn);
    const int  j   = g_nbr[row];

    const float p0 = __fsub_rn(pos[(size_t)j*3+0], g_centers[(size_t)ci*3+0]);
    const float p1 = __fsub_rn(pos[(size_t)j*3+1], g_centers[(size_t)ci*3+1]);
    const float p2 = __fsub_rn(pos[(size_t)j*3+2], g_centers[(size_t)ci*3+2]);

    const float* xr = xwb + (size_t)j * c1;
    float* hr = h1 + (size_t)row * c1;
#pragma unroll 2
    for (int c = lane; c < c1; c += 32) {
        float v = xr[c];
        v = fmaf(p0, s_wp[c],        v);
        v = fmaf(p1, s_wp[c1 + c],   v);
        v = fmaf(p2, s_wp[2*c1 + c], v);
        hr[c] = fmaxf(v, 0.f);
    }
}

// =================================================================================
// 6) new_pos / new_batch tail
// =================================================================================
__global__ void tail_kernel(float* __restrict__ out, int writePos, int writeBatch)
{
    int i = blockIdx.x * blockDim.x + threadIdx.x;
    if (i >= NC) return;
    if (writePos) {
        out[OUT_POS_OFF + i*3 + 0] = g_centers[i*3+0];
        out[OUT_POS_OFF + i*3 + 1] = g_centers[i*3+1];
        out[OUT_POS_OFF + i*3 + 2] = g_centers[i*3+2];
    }
    if (writeBatch) out[OUT_BATCH_OFF + i] = (float)(i / SS);
}

// =================================================================================
extern "C" void kernel_launch(void* const* d_in, const int* in_sizes, int n_in,
                              void* d_out, int out_size)
{
    const float* x   = (const float*)d_in[0];
    const float* pos = (const float*)d_in[1];
    const float* W[3][3];
    const float* bv[3][3];
    int ii = 3;
    for (int s = 0; s < 3; s++)
        for (int l = 0; l < 3; l++) {
            W[s][l]  = (const float*)d_in[ii++];
            bv[s][l] = (const float*)d_in[ii++];
        }
    float* out = (float*)d_out;

    void *pA = nullptr, *pB = nullptr, *pX = nullptr;
    cudaGetSymbolAddress(&pA, g_bufA);
    cudaGetSymbolAddress(&pB, g_bufB);
    cudaGetSymbolAddress(&pX, g_xw);
    float* bufA = (float*)pA;   // h2
    float* bufB = (float*)pB;   // h1
    float* xw   = (float*)pX;

    const int   Kl[3]   = {16, 32, 64};
    const float r2l[3]  = {(float)(0.1*0.1), (float)(0.2*0.2), (float)(0.4*0.4)};
    const int   c1[3]   = {64, 128, 128};
    const int   c2[3]   = {64, 128, 128};
    const int   c3[3]   = {128, 256, 256};
    const int   coff[3] = {0, 128, 384};
    const size_t xwOff[3] = {0, (size_t)NPTS*64, (size_t)NPTS*(64+128)};

    // precompute xwb_s = x @ W_s[0:64,:] + b_s   (independent of FPS)
    for (int s = 0; s < 3; s++)
        gemm_db<<<dim3(NPTS/128, c1[s]/64), 128>>>(x, W[s][0], bv[s][0],
                                                   xw + xwOff[s], 64, c1[s], 0);

    fps_kernel<<<BB, 512>>>(pos);

    const int writePos   = (out_size >= OUT_POS_OFF + NC*3);
    const int writeBatch = (out_size >= OUT_BATCH_OFF + NC);
    tail_kernel<<<(NC + 255)/256, 256>>>(out, writePos, writeBatch);

    for (int s = 0; s < 3; s++) {
        const int K = Kl[s];
        const int R = NC * K;
        nbr_kernel<<<NC, 256>>>(pos, r2l[s], K);
        fused_l1<<<R/8, 256>>>(pos, xw + xwOff[s], W[s][0], K, c1[s], bufB);
        gemm_db<<<dim3(R/128, c2[s]/64), 128>>>(bufB, W[s][1], bv[s][1], bufA,
                                                c1[s], c2[s], 1);
        gemm_db_max<<<dim3(R/128, c3[s]/64), 128>>>(bufA, W[s][2], bv[s][2], out,
                                                    c2[s], c3[s], K, coff[s]);
    }
}

// round 3
// speedup vs baseline: 1.6728x; 1.0791x over previous
#include <cuda_runtime.h>
#include <cstdint>

#define BB  8
#define NN  4096
#define SS  1024
#define CIN 64
#define NC  (BB*SS)          /* 8192 centers */
#define NPTS (BB*NN)         /* 32768 points */

#define OUT_X_ELEMS   (NC*640)
#define OUT_POS_OFF   OUT_X_ELEMS
#define OUT_BATCH_OFF (OUT_X_ELEMS + NC*3)

#define INF_F __int_as_float(0x7f800000)

// ---------------- scratch (__device__ globals: allocation-free contract) ---------
__device__ float g_centers[NC*3];
__device__ int   g_nbr[NC*64];
__device__ int   g_cnt[NC];
__device__ float g_xw[(size_t)NPTS*320];      // 42 MB: x@Wx + b, all 3 scales
__device__ float g_bufA[(size_t)NC*64*128];   // 268 MB: h2
__device__ float g_bufB[(size_t)NC*64*128];   // 268 MB: h1

// =================================================================================
// 1) Farthest point sampling. Distance arithmetic is bitwise-frozen:
//    ((dx*dx + dy*dy) + dz*dz), all __f*_rn, no FMA; fminf; first-max argmax.
//    Reduction via REDUX.SYNC.MAX.U32 on positive-float bits (order-isomorphic);
//    ties -> lowest lane via ballot/ffs = smallest index (lane order == idx order).
// =================================================================================
__global__ void __launch_bounds__(512) fps_kernel(const float* __restrict__ pos)
{
    const int b   = blockIdx.x;
    const int tid = threadIdx.x;
    const float* p = pos + (size_t)b * NN * 3;

    __shared__ float s_xyz[NN*3];      // 48KB: positions for fast center fetch
    __shared__ float s_c[3];
    __shared__ float s_v[16];
    __shared__ int   s_i[16];

    for (int i = tid; i < NN*3; i += 512) s_xyz[i] = p[i];

    float px[8], py[8], pz[8], md[8];
#pragma unroll
    for (int i = 0; i < 8; i++) {
        int j = tid * 8 + i;
        px[i] = p[j*3+0]; py[i] = p[j*3+1]; pz[i] = p[j*3+2];
        md[i] = INF_F;
    }

    if (tid == 0) {
        s_c[0] = p[0]; s_c[1] = p[1]; s_c[2] = p[2];
        size_t o = (size_t)b * SS * 3;
        g_centers[o] = p[0]; g_centers[o+1] = p[1]; g_centers[o+2] = p[2];
    }
    __syncthreads();

    for (int s = 1; s < SS; s++) {
        const float cx = s_c[0], cy = s_c[1], cz = s_c[2];
        float bv = -1.0f; int bi = 0;
#pragma unroll
        for (int i = 0; i < 8; i++) {
            float dx = __fsub_rn(px[i], cx);
            float dy = __fsub_rn(py[i], cy);
            float dz = __fsub_rn(pz[i], cz);
            float d2 = __fadd_rn(__fadd_rn(__fmul_rn(dx,dx), __fmul_rn(dy,dy)),
                                 __fmul_rn(dz,dz));
            md[i] = fminf(md[i], d2);
            if (md[i] > bv) { bv = md[i]; bi = tid*8 + i; }
        }
        // warp argmax: redux on bits (bv >= 0 always), lowest-lane tie-break
        unsigned ubv  = __float_as_uint(bv);
        unsigned wmax = __reduce_max_sync(0xffffffffu, ubv);
        unsigned ball = __ballot_sync(0xffffffffu, ubv == wmax);
        int src = __ffs(ball) - 1;
        int wbi = __shfl_sync(0xffffffffu, bi, src);
        if ((tid & 31) == 0) { s_v[tid>>5] = __uint_as_float(wmax); s_i[tid>>5] = wbi; }
        __syncthreads();

        if (tid < 32) {
            unsigned v = (tid < 16) ? __float_as_uint(s_v[tid]) : 0u;
            int      i = (tid < 16) ? s_i[tid] : 0;
            unsigned m  = __reduce_max_sync(0xffffffffu, v);
            unsigned ba = __ballot_sync(0xffffffffu, v == m);
            int sc = __ffs(ba) - 1;
            int i2 = __shfl_sync(0xffffffffu, i, sc);
            if (tid == 0) {
                float nx = s_xyz[i2*3+0], ny = s_xyz[i2*3+1], nz = s_xyz[i2*3+2];
                s_c[0] = nx; s_c[1] = ny; s_c[2] = nz;
                size_t o = ((size_t)b*SS + s) * 3;
                g_centers[o] = nx; g_centers[o+1] = ny; g_centers[o+2] = nz;
            }
        }
        __syncthreads();
    }
}

// =================================================================================
// 2) Radius ball query + exact top-K (unchanged)
// =================================================================================
__global__ void __launch_bounds__(256) nbr_kernel(const float* __restrict__ pos,
                                                  float r2, int Kn)
{
    __shared__ unsigned long long keys[4096];
    __shared__ int s_count;
    const int ci  = blockIdx.x;
    const int b   = ci / SS;
    const int tid = threadIdx.x;
    if (tid == 0) s_count = 0;
    __syncthreads();

    const float cx = g_centers[ci*3+0], cy = g_centers[ci*3+1], cz = g_centers[ci*3+2];
    const float* p = pos + (size_t)b * NN * 3;

    for (int j = tid; j < NN; j += 256) {
        float dx = __fsub_rn(cx, p[j*3+0]);
        float dy = __fsub_rn(cy, p[j*3+1]);
        float dz = __fsub_rn(cz, p[j*3+2]);
        float d2 = __fadd_rn(__fadd_rn(__fmul_rn(dx,dx), __fmul_rn(dy,dy)),
                             __fmul_rn(dz,dz));
        if (d2 <= r2) {
            int w = atomicAdd(&s_count, 1);
            keys[w] = (((unsigned long long)__float_as_uint(d2)) << 32) | (unsigned)j;
        }
    }
    __syncthreads();
    const int M = s_count;
    int n = 16;
    while (n < M || n < Kn) n <<= 1;
    for (int i = M + tid; i < n; i += 256) keys[i] = 0xFFFFFFFFFFFFFFFFULL;
    __syncthreads();

    for (int size = 2; size <= n; size <<= 1) {
        for (int stride = size >> 1; stride > 0; stride >>= 1) {
            for (int i = tid; i < (n >> 1); i += 256) {
                int p0 = 2*i - (i & (stride - 1));
                int p1 = p0 + stride;
                unsigned long long a = keys[p0], c = keys[p1];
                bool asc = ((p0 & size) == 0);
                if (asc ? (a > c) : (a < c)) { keys[p0] = c; keys[p1] = a; }
            }
            __syncthreads();
        }
    }

    for (int k = tid; k < Kn; k += 256) {
        int j = (k < M) ? (int)(keys[k] & 0xFFFFFFFFu) : 0;
        g_nbr[(size_t)ci * Kn + k] = b * NN + j;
    }
    if (tid == 0) g_cnt[ci] = (M < Kn) ? M : Kn;
}

// =================================================================================
// 3) Double-buffered fp32 GEMM (+bias, optional ReLU). Unchanged.
// =================================================================================
__global__ void __launch_bounds__(128) gemm_db(const float* __restrict__ A,
                                               const float* __restrict__ W,
                                               const float* __restrict__ bias,
                                               float* __restrict__ C,
                                               int Kc, int Nc, int doRelu)
{
    __shared__ float As[2][16][128];
    __shared__ float Bs[2][16][64];
    const int tid = threadIdx.x;
    const int tx  = tid & 7, ty = tid >> 3;
    const int row0 = blockIdx.x * 128;
    const int col0 = blockIdx.y * 64;

    float acc[8][8];
#pragma unroll
    for (int i = 0; i < 8; i++)
#pragma unroll
        for (int j = 0; j < 8; j++) acc[i][j] = 0.f;

    float regA[16], regB[8];
    const float* Arow = A + (size_t)(row0 + tid) * Kc;
    const int bk = tid >> 3;
    const int bn = (tid & 7) * 8;

#pragma unroll
    for (int q = 0; q < 4; q++)
        *(float4*)&regA[q*4] = *(const float4*)&Arow[q*4];
    {
        const float* Wr = W + (size_t)bk * Nc + col0 + bn;
        *(float4*)&regB[0] = *(const float4*)&Wr[0];
        *(float4*)&regB[4] = *(const float4*)&Wr[4];
    }

    int buf = 0;
    for (int kk = 0; kk < Kc; kk += 16) {
#pragma unroll
        for (int t = 0; t < 16; t++) As[buf][t][tid] = regA[t];
        *(float4*)&Bs[buf][bk][bn]   = *(float4*)&regB[0];
        *(float4*)&Bs[buf][bk][bn+4] = *(float4*)&regB[4];
        __syncthreads();

        if (kk + 16 < Kc) {
#pragma unroll
            for (int q = 0; q < 4; q++)
                *(float4*)&regA[q*4] = *(const float4*)&Arow[kk + 16 + q*4];
            const float* Wr = W + (size_t)(kk + 16 + bk) * Nc + col0 + bn;
            *(float4*)&regB[0] = *(const float4*)&Wr[0];
            *(float4*)&regB[4] = *(const float4*)&Wr[4];
        }

#pragma unroll
        for (int k = 0; k < 16; k++) {
            float a[8], b2[8];
            *(float4*)&a[0]  = *(const float4*)&As[buf][k][ty*8];
            *(float4*)&a[4]  = *(const float4*)&As[buf][k][ty*8+4];
            *(float4*)&b2[0] = *(const float4*)&Bs[buf][k][tx*8];
            *(float4*)&b2[4] = *(const float4*)&Bs[buf][k][tx*8+4];
#pragma unroll
            for (int i = 0; i < 8; i++)
#pragma unroll
                for (int j = 0; j < 8; j++)
                    acc[i][j] = fmaf(a[i], b2[j], acc[i][j]);
        }
        buf ^= 1;
    }

#pragma unroll
    for (int j = 0; j < 8; j++) {
        float bj = bias[col0 + tx*8 + j];
#pragma unroll
        for (int i = 0; i < 8; i++) {
            float v = acc[i][j] + bj;
            if (doRelu) v = fmaxf(v, 0.f);
            C[(size_t)(row0 + ty*8 + i) * Nc + col0 + tx*8 + j] = v;
        }
    }
}

// =================================================================================
// 4) Last-layer GEMM + bias + ReLU + masked segment-max (unchanged)
// =================================================================================
__global__ void __launch_bounds__(128) gemm_db_max(const float* __restrict__ A,
                                                   const float* __restrict__ W,
                                                   const float* __restrict__ bias,
                                                   float* __restrict__ out,
                                                   int Kc, int Nc, int Kn, int colOff)
{
    __shared__ float As[2][16][128];
    __shared__ float Bs[2][16][64];
    __shared__ float red[16][64];
    const int tid = threadIdx.x;
    const int tx  = tid & 7, ty = tid >> 3;
    const int row0 = blockIdx.x * 128;
    const int col0 = blockIdx.y * 64;

    float acc[8][8];
#pragma unroll
    for (int i = 0; i < 8; i++)
#pragma unroll
        for (int j = 0; j < 8; j++) acc[i][j] = 0.f;

    float regA[16], regB[8];
    const float* Arow = A + (size_t)(row0 + tid) * Kc;
    const int bk = tid >> 3;
    const int bn = (tid & 7) * 8;

#pragma unroll
    for (int q = 0; q < 4; q++)
        *(float4*)&regA[q*4] = *(const float4*)&Arow[q*4];
    {
        const float* Wr = W + (size_t)bk * Nc + col0 + bn;
        *(float4*)&regB[0] = *(const float4*)&Wr[0];
        *(float4*)&regB[4] = *(const float4*)&Wr[4];
    }

    int buf = 0;
    for (int kk = 0; kk < Kc; kk += 16) {
#pragma unroll
        for (int t = 0; t < 16; t++) As[buf][t][tid] = regA[t];
        *(float4*)&Bs[buf][bk][bn]   = *(float4*)&regB[0];
        *(float4*)&Bs[buf][bk][bn+4] = *(float4*)&regB[4];
        __syncthreads();

        if (kk + 16 < Kc) {
#pragma unroll
            for (int q = 0; q < 4; q++)
                *(float4*)&regA[q*4] = *(const float4*)&Arow[kk + 16 + q*4];
            const float* Wr = W + (size_t)(kk + 16 + bk) * Nc + col0 + bn;
            *(float4*)&regB[0] = *(const float4*)&Wr[0];
            *(float4*)&regB[4] = *(const float4*)&Wr[4];
        }

#pragma unroll
        for (int k = 0; k < 16; k++) {
            float a[8], b2[8];
            *(float4*)&a[0]  = *(const float4*)&As[buf][k][ty*8];
            *(float4*)&a[4]  = *(const float4*)&As[buf][k][ty*8+4];
            *(float4*)&b2[0] = *(const float4*)&Bs[buf][k][tx*8];
            *(float4*)&b2[4] = *(const float4*)&Bs[buf][k][tx*8+4];
#pragma unroll
            for (int i = 0; i < 8; i++)
#pragma unroll
                for (int j = 0; j < 8; j++)
                    acc[i][j] = fmaf(a[i], b2[j], acc[i][j]);
        }
        buf ^= 1;
    }

    const int cglob = (row0 + ty*8) / Kn;
    const int ccnt  = g_cnt[cglob];
    float bj[8];
#pragma unroll
    for (int j = 0; j < 8; j++) bj[j] = bias[col0 + tx*8 + j];
    float m[8];
#pragma unroll
    for (int j = 0; j < 8; j++) m[j] = -INF_F;
#pragma unroll
    for (int i = 0; i < 8; i++) {
        int kidx = (ty*8 + i) % Kn;
        if (kidx < ccnt) {
#pragma unroll
            for (int j = 0; j < 8; j++)
                m[j] = fmaxf(m[j], fmaxf(acc[i][j] + bj[j], 0.f));
        }
    }
    __syncthreads();
#pragma unroll
    for (int j = 0; j < 8; j++) red[ty][tx*8 + j] = m[j];
    __syncthreads();

    const int tper = Kn >> 3;
    if ((ty & (tper - 1)) == 0) {
#pragma unroll
        for (int j = 0; j < 8; j++) {
            float v = red[ty][tx*8 + j];
            for (int t = 1; t < tper; t++) v = fmaxf(v, red[ty + t][tx*8 + j]);
            out[(size_t)cglob * 640 + colOff + col0 + tx*8 + j] = v;
        }
    }
}

// =================================================================================
// 5) Fused gather + layer-1 (unchanged)
// =================================================================================
__global__ void __launch_bounds__(256) fused_l1(const float* __restrict__ pos,
                                                const float* __restrict__ xwb,
                                                const float* __restrict__ W1,
                                                int Kn, int c1,
                                                float* __restrict__ h1)
{
    __shared__ float s_wp[3*128];
    const int tid  = threadIdx.x;
    for (int i = tid; i < 3 * c1; i += 256)
        s_wp[i] = W1[(size_t)(64 + i / c1) * c1 + (i % c1)];
    __syncthreads();

    const int warp = tid >> 5, lane = tid & 31;
    const long row = (long)blockIdx.x * 8 + warp;
    const int  ci  = (int)(row / Kn);
    const int  j   = g_nbr[row];

    const float p0 = __fsub_rn(pos[(size_t)j*3+0], g_centers[(size_t)ci*3+0]);
    const float p1 = __fsub_rn(pos[(size_t)j*3+1], g_centers[(size_t)ci*3+1]);
    const float p2 = __fsub_rn(pos[(size_t)j*3+2], g_centers[(size_t)ci*3+2]);

    const float* xr = xwb + (size_t)j * c1;
    float* hr = h1 + (size_t)row * c1;
#pragma unroll 2
    for (int c = lane; c < c1; c += 32) {
        float v = xr[c];
        v = fmaf(p0, s_wp[c],        v);
        v = fmaf(p1, s_wp[c1 + c],   v);
        v = fmaf(p2, s_wp[2*c1 + c], v);
        hr[c] = fmaxf(v, 0.f);
    }
}

// =================================================================================
// 6) new_pos / new_batch tail
// =================================================================================
__global__ void tail_kernel(float* __restrict__ out, int writePos, int writeBatch)
{
    int i = blockIdx.x * blockDim.x + threadIdx.x;
    if (i >= NC) return;
    if (writePos) {
        out[OUT_POS_OFF + i*3 + 0] = g_centers[i*3+0];
        out[OUT_POS_OFF + i*3 + 1] = g_centers[i*3+1];
        out[OUT_POS_OFF + i*3 + 2] = g_centers[i*3+2];
    }
    if (writeBatch) out[OUT_BATCH_OFF + i] = (float)(i / SS);
}

// =================================================================================
extern "C" void kernel_launch(void* const* d_in, const int* in_sizes, int n_in,
                              void* d_out, int out_size)
{
    const float* x   = (const float*)d_in[0];
    const float* pos = (const float*)d_in[1];
    const float* W[3][3];
    const float* bv[3][3];
    int ii = 3;
    for (int s = 0; s < 3; s++)
        for (int l = 0; l < 3; l++) {
            W[s][l]  = (const float*)d_in[ii++];
            bv[s][l] = (const float*)d_in[ii++];
        }
    float* out = (float*)d_out;

    void *pA = nullptr, *pB = nullptr, *pX = nullptr;
    cudaGetSymbolAddress(&pA, g_bufA);
    cudaGetSymbolAddress(&pB, g_bufB);
    cudaGetSymbolAddress(&pX, g_xw);
    float* bufA = (float*)pA;   // h2
    float* bufB = (float*)pB;   // h1
    float* xw   = (float*)pX;

    const int   Kl[3]   = {16, 32, 64};
    const float r2l[3]  = {(float)(0.1*0.1), (float)(0.2*0.2), (float)(0.4*0.4)};
    const int   c1[3]   = {64, 128, 128};
    const int   c2[3]   = {64, 128, 128};
    const int   c3[3]   = {128, 256, 256};
    const int   coff[3] = {0, 128, 384};
    const size_t xwOff[3] = {0, (size_t)NPTS*64, (size_t)NPTS*(64+128)};

    for (int s = 0; s < 3; s++)
        gemm_db<<<dim3(NPTS/128, c1[s]/64), 128>>>(x, W[s][0], bv[s][0],
                                                   xw + xwOff[s], 64, c1[s], 0);

    fps_kernel<<<BB, 512>>>(pos);

    const int writePos   = (out_size >= OUT_POS_OFF + NC*3);
    const int writeBatch = (out_size >= OUT_BATCH_OFF + NC);
    tail_kernel<<<(NC + 255)/256, 256>>>(out, writePos, writeBatch);

    for (int s = 0; s < 3; s++) {
        const int K = Kl[s];
        const int R = NC * K;
        nbr_kernel<<<NC, 256>>>(pos, r2l[s], K);
        fused_l1<<<R/8, 256>>>(pos, xw + xwOff[s], W[s][0], K, c1[s], bufB);
        gemm_db<<<dim3(R/128, c2[s]/64), 128>>>(bufB, W[s][1], bv[s][1], bufA,
                                                c1[s], c2[s], 1);
        gemm_db_max<<<dim3(R/128, c3[s]/64), 128>>>(bufA, W[s][2], bv[s][2], out,
                                                    c2[s], c3[s], K, coff[s]);
    }
}